// round 1
// baseline (speedup 1.0000x reference)
#include <cuda_runtime.h>
#include <math.h>

// ---------------------------------------------------------------------------
// MS-SSIM on (32,3,512,512) fp32 image pairs, 5 pyramid levels.
// Per level: fused tiled kernel = separable 5x5 Gaussian moments + per-pixel
// SSIM/CS + block reduction + 2x2 avg-pool for next level.
// ---------------------------------------------------------------------------

#define NC 96              // N*C = 32*3 planes
#define TILE 32

// per-plane element counts at levels 1..4 (outputs of pooling)
#define L1_PER 65536       // 256*256
#define L2_PER 16384       // 128*128
#define L3_PER 4096        // 64*64
#define L4_PER 1024        // 32*32

#define OFF_L1 0
#define OFF_L2 (NC * L1_PER)                       // 6291456
#define OFF_L3 (OFF_L2 + NC * L2_PER)              // 7864320
#define OFF_L4 (OFF_L3 + NC * L3_PER)              // 8257536
#define BUF_TOT (OFF_L4 + NC * L4_PER)             // 8355840 floats (~33.4MB)

__device__ float g_b1[BUF_TOT];
__device__ float g_b2[BUF_TOT];
__device__ double g_acc_ssim[5];
__device__ double g_acc_cs[5];

// Gaussian(sigma=1.5) 5-tap, normalized (matches reference make_window)
#define GW0 0.12007838424321349f
#define GW1 0.23388075658535032f
#define GW2 0.29208171834287243f

__global__ void zero_acc_kernel() {
    int i = threadIdx.x;
    if (i < 5) { g_acc_ssim[i] = 0.0; g_acc_cs[i] = 0.0; }
}

__global__ void __launch_bounds__(256)
ssim_level_kernel(const float* __restrict__ ext1, const float* __restrict__ ext2,
                  int inOff, int outOff, int W, int H, int level, int writePool)
{
    __shared__ float s1[36][36];
    __shared__ float s2[36][36];
    __shared__ float hb[5][36][32];
    __shared__ float red[2][8];

    const float gw[5] = {GW0, GW1, GW2, GW1, GW0};

    const int tx = threadIdx.x, ty = threadIdx.y;
    const int tid = ty * 32 + tx;
    const int ox = blockIdx.x * TILE, oy = blockIdx.y * TILE;
    const int plane = blockIdx.z;

    const size_t planeOff = (size_t)plane * W * H;
    const float* p1 = ext1 ? (ext1 + planeOff) : (g_b1 + inOff + planeOff);
    const float* p2 = ext2 ? (ext2 + planeOff) : (g_b2 + inOff + planeOff);

    // ---- load 36x36 halo tiles (zero padding outside image) ----
    for (int idx = tid; idx < 36 * 36; idx += 256) {
        int r = idx / 36, c = idx % 36;
        int gy = oy + r - 2, gx = ox + c - 2;
        bool ok = (gy >= 0) & (gy < H) & (gx >= 0) & (gx < W);
        float v1 = 0.f, v2 = 0.f;
        if (ok) {
            size_t g = (size_t)gy * W + gx;
            v1 = p1[g]; v2 = p2[g];
        }
        s1[r][c] = v1; s2[r][c] = v2;
    }
    __syncthreads();

    // ---- horizontal Gaussian pass over 5 moment images ----
    for (int r = ty; r < 36; r += 8) {
        float a0 = 0.f, a1 = 0.f, a2 = 0.f, a3 = 0.f, a4 = 0.f;
        #pragma unroll
        for (int k = 0; k < 5; k++) {
            float x = s1[r][tx + k];
            float y = s2[r][tx + k];
            float w = gw[k];
            a0 += w * x;
            a1 += w * y;
            a2 += w * x * x;
            a3 += w * y * y;
            a4 += w * x * y;
        }
        hb[0][r][tx] = a0; hb[1][r][tx] = a1; hb[2][r][tx] = a2;
        hb[3][r][tx] = a3; hb[4][r][tx] = a4;
    }
    __syncthreads();

    // ---- vertical pass + per-pixel SSIM / CS ----
    const float C1 = 0.01f * 0.01f;
    const float C2 = 0.03f * 0.03f;
    float ssim_acc = 0.f, cs_acc = 0.f;

    #pragma unroll
    for (int i = 0; i < 4; i++) {
        int r = ty + 8 * i;   // output row within tile (0..31)
        float mu1 = 0.f, mu2 = 0.f, e11 = 0.f, e22 = 0.f, e12 = 0.f;
        #pragma unroll
        for (int k = 0; k < 5; k++) {
            float w = gw[k];
            mu1 += w * hb[0][r + k][tx];
            mu2 += w * hb[1][r + k][tx];
            e11 += w * hb[2][r + k][tx];
            e22 += w * hb[3][r + k][tx];
            e12 += w * hb[4][r + k][tx];
        }
        float mu1sq = mu1 * mu1;
        float mu2sq = mu2 * mu2;
        float mu12  = mu1 * mu2;
        float sg11 = e11 - mu1sq;
        float sg22 = e22 - mu2sq;
        float sg12 = e12 - mu12;
        float csn = 2.f * sg12 + C2;
        float csd = sg11 + sg22 + C2;
        float cs = csn / csd;
        float ssim = ((2.f * mu12 + C1) * csn) / ((mu1sq + mu2sq + C1) * csd);
        ssim_acc += ssim;
        cs_acc += cs;
    }

    // ---- fused 2x2 avg-pool -> next level buffers ----
    if (writePool) {
        int pr = tid >> 4, pc = tid & 15;     // 16x16 pooled outputs per tile
        int r0 = 2 + 2 * pr, c0 = 2 + 2 * pc; // interior (unpadded) region
        float v1 = 0.25f * (s1[r0][c0] + s1[r0][c0 + 1] + s1[r0 + 1][c0] + s1[r0 + 1][c0 + 1]);
        float v2 = 0.25f * (s2[r0][c0] + s2[r0][c0 + 1] + s2[r0 + 1][c0] + s2[r0 + 1][c0 + 1]);
        int Wh = W >> 1, Hh = H >> 1;
        size_t o = (size_t)outOff + (size_t)plane * Wh * Hh
                 + (size_t)(oy / 2 + pr) * Wh + (ox / 2 + pc);
        g_b1[o] = v1;
        g_b2[o] = v2;
    }

    // ---- block reduction -> global double accumulators ----
    #pragma unroll
    for (int off = 16; off; off >>= 1) {
        ssim_acc += __shfl_down_sync(0xffffffffu, ssim_acc, off);
        cs_acc   += __shfl_down_sync(0xffffffffu, cs_acc, off);
    }
    if (tx == 0) { red[0][ty] = ssim_acc; red[1][ty] = cs_acc; }
    __syncthreads();
    if (tid == 0) {
        float s = 0.f, c = 0.f;
        #pragma unroll
        for (int i = 0; i < 8; i++) { s += red[0][i]; c += red[1][i]; }
        atomicAdd(&g_acc_ssim[level], (double)s);
        atomicAdd(&g_acc_cs[level], (double)c);
    }
}

__global__ void finalize_kernel(float* __restrict__ out)
{
    // weights as float32 (matching reference MS_WEIGHTS dtype), lifted to double
    const double w[5] = {(double)0.0448f, (double)0.2856f, (double)0.3001f,
                         (double)0.2363f, (double)0.1333f};
    // level 4 ssim term
    double cnt4 = (double)NC * 32.0 * 32.0;
    double s4 = g_acc_ssim[4] / cnt4;
    double ss4 = (s4 + 1.0) * 0.5;
    double p2 = pow(ss4, w[4]);   // pow2[-1]

    double res = 1.0;
    #pragma unroll
    for (int i = 0; i < 4; i++) {
        int dim = 512 >> i;
        double cnt = (double)NC * (double)dim * (double)dim;
        double cs = g_acc_cs[i] / cnt;
        double m = (cs + 1.0) * 0.5;
        res *= pow(m, w[i]) * p2;  // prod(pow1[:-1] * pow2[-1])
    }
    out[0] = (float)res;
}

extern "C" void kernel_launch(void* const* d_in, const int* in_sizes, int n_in,
                              void* d_out, int out_size)
{
    const float* img1 = (const float*)d_in[0];
    const float* img2 = (const float*)d_in[1];
    float* out = (float*)d_out;

    zero_acc_kernel<<<1, 32>>>();

    dim3 blk(32, 8);
    // level 0: 512x512, inputs from harness, pool -> L1
    ssim_level_kernel<<<dim3(16, 16, NC), blk>>>(img1, img2, 0, OFF_L1, 512, 512, 0, 1);
    // level 1: 256x256 -> L2
    ssim_level_kernel<<<dim3(8, 8, NC), blk>>>(nullptr, nullptr, OFF_L1, OFF_L2, 256, 256, 1, 1);
    // level 2: 128x128 -> L3
    ssim_level_kernel<<<dim3(4, 4, NC), blk>>>(nullptr, nullptr, OFF_L2, OFF_L3, 128, 128, 2, 1);
    // level 3: 64x64 -> L4
    ssim_level_kernel<<<dim3(2, 2, NC), blk>>>(nullptr, nullptr, OFF_L3, OFF_L4, 64, 64, 3, 1);
    // level 4: 32x32, no pooling output
    ssim_level_kernel<<<dim3(1, 1, NC), blk>>>(nullptr, nullptr, OFF_L4, 0, 32, 32, 4, 0);

    finalize_kernel<<<1, 1>>>(out);
}

// round 2
// speedup vs baseline: 1.1149x; 1.1149x over previous
#include <cuda_runtime.h>
#include <math.h>

// ---------------------------------------------------------------------------
// MS-SSIM on (32,3,512,512) fp32, 5 levels.
// L0, L1: tiled kernel (32x32 tile, float2-packed pixels, float4-packed
//         moments, register-ring vertical pass, fused 2x2 pool).
// L2+L3+L4: single fused kernel, whole 128x128 plane (+ pooled 64/32) in
//         dynamic SMEM, 96 blocks.
// ---------------------------------------------------------------------------

#define NC 96
#define L1_PER 65536            // 256*256
#define L2_PER 16384            // 128*128
#define OFF_L1 0
#define OFF_L2 (NC * L1_PER)
#define BUF_TOT (OFF_L2 + NC * L2_PER)

__device__ float g_b1[BUF_TOT];
__device__ float g_b2[BUF_TOT];
__device__ double g_acc_ssim[5];
__device__ double g_acc_cs[5];

// Gaussian(sigma=1.5) 5-tap normalized
#define GW0 0.12007838424321349f
#define GW1 0.23388075658535032f
#define GW2 0.29208171834287243f
#define C1V (0.01f * 0.01f)
#define C2V (0.03f * 0.03f)

__global__ void zero_acc_kernel() {
    int i = threadIdx.x;
    if (i < 5) { g_acc_ssim[i] = 0.0; g_acc_cs[i] = 0.0; }
}

__device__ __forceinline__ void ssim_px(float mu1, float mu2, float e11,
                                        float e22, float e12,
                                        float& sacc, float& cacc)
{
    float mu1sq = mu1 * mu1;
    float mu2sq = mu2 * mu2;
    float mu12  = mu1 * mu2;
    float sg11 = e11 - mu1sq;
    float sg22 = e22 - mu2sq;
    float sg12 = e12 - mu12;
    float csn = 2.f * sg12 + C2V;
    float csd = sg11 + sg22 + C2V;
    float lnum = 2.f * mu12 + C1V;
    float lden = mu1sq + mu2sq + C1V;
    float cs = __fdividef(csn, csd);
    sacc += __fdividef(lnum, lden) * cs;
    cacc += cs;
}

// ---------------------------------------------------------------------------
// Big-level kernel (levels 0 and 1)
// ---------------------------------------------------------------------------
__global__ void __launch_bounds__(256)
ssim_big(const float* __restrict__ ext1, const float* __restrict__ ext2,
         int inOff, int outOff, int W, int H, int level)
{
    __shared__ float2 s[36][36];        // packed (img1, img2) halo tile
    __shared__ float4 hb4[36][32];      // (mu1h, mu2h, e11h, e22h)
    __shared__ float  hb1[36][32];      // e12h
    __shared__ float  red[2][8];

    const float gw[5] = {GW0, GW1, GW2, GW1, GW0};

    const int tx = threadIdx.x, ty = threadIdx.y;
    const int tid = ty * 32 + tx;
    const int ox = blockIdx.x * 32, oy = blockIdx.y * 32;
    const int plane = blockIdx.z;

    const size_t planeOff = (size_t)plane * W * H;
    const float* p1 = ext1 ? (ext1 + planeOff) : (g_b1 + inOff + planeOff);
    const float* p2 = ext2 ? (ext2 + planeOff) : (g_b2 + inOff + planeOff);

    // ---- stage 1: load 36x36 halo (float2-packed) ----
    bool interior = (ox >= 2) & (oy >= 2) & (ox + 34 <= W) & (oy + 34 <= H);
    if (interior) {
        #pragma unroll
        for (int it = 0; it < 6; it++) {
            int idx = tid + it * 256;
            if (idx < 1296) {
                int r = idx / 36, c = idx - 36 * r;
                size_t g = (size_t)(oy + r - 2) * W + (ox + c - 2);
                s[r][c] = make_float2(p1[g], p2[g]);
            }
        }
    } else {
        #pragma unroll
        for (int it = 0; it < 6; it++) {
            int idx = tid + it * 256;
            if (idx < 1296) {
                int r = idx / 36, c = idx - 36 * r;
                int gy = oy + r - 2, gx = ox + c - 2;
                float2 v = make_float2(0.f, 0.f);
                if ((gy >= 0) & (gy < H) & (gx >= 0) & (gx < W)) {
                    size_t g = (size_t)gy * W + gx;
                    v = make_float2(p1[g], p2[g]);
                }
                s[r][c] = v;
            }
        }
    }
    __syncthreads();

    // ---- stage 2: horizontal Gaussian moments ----
    for (int r = ty; r < 36; r += 8) {
        const float2* row = &s[r][tx];
        float m0 = 0.f, m1 = 0.f, m2 = 0.f, m3 = 0.f, m4 = 0.f;
        #pragma unroll
        for (int k = 0; k < 5; k++) {
            float2 v = row[k];
            float w = gw[k];
            m0 += w * v.x;
            m1 += w * v.y;
            m2 += w * (v.x * v.x);
            m3 += w * (v.y * v.y);
            m4 += w * (v.x * v.y);
        }
        hb4[r][tx] = make_float4(m0, m1, m2, m3);
        hb1[r][tx] = m4;
    }
    __syncthreads();

    // ---- fused 2x2 avg-pool -> next level (reads s, independent of stage 3) ----
    {
        int pr = tid >> 4, pc = tid & 15;
        int r0 = 2 + 2 * pr, c0 = 2 + 2 * pc;
        float2 a = s[r0][c0], b = s[r0][c0 + 1];
        float2 c = s[r0 + 1][c0], d = s[r0 + 1][c0 + 1];
        int Wh = W >> 1, Hh = H >> 1;
        size_t o = (size_t)outOff + (size_t)plane * Wh * Hh
                 + (size_t)(oy / 2 + pr) * Wh + (ox / 2 + pc);
        g_b1[o] = 0.25f * (a.x + b.x + c.x + d.x);
        g_b2[o] = 0.25f * (a.y + b.y + c.y + d.y);
    }

    // ---- stage 3: vertical pass via register ring, 4 consecutive rows/thread ----
    const int b = ty * 4;
    float4 q[5]; float e[5];
    #pragma unroll
    for (int j = 0; j < 5; j++) { q[j] = hb4[b + j][tx]; e[j] = hb1[b + j][tx]; }

    float sacc = 0.f, cacc = 0.f;
    #pragma unroll
    for (int i = 0; i < 4; i++) {
        if (i > 0) {
            int sl = (i + 4) % 5;
            q[sl] = hb4[b + i + 4][tx];
            e[sl] = hb1[b + i + 4][tx];
        }
        float mu1 = 0.f, mu2 = 0.f, e11 = 0.f, e22 = 0.f, e12 = 0.f;
        #pragma unroll
        for (int k = 0; k < 5; k++) {
            int sl = (i + k) % 5;
            float w = gw[k];
            mu1 += w * q[sl].x;
            mu2 += w * q[sl].y;
            e11 += w * q[sl].z;
            e22 += w * q[sl].w;
            e12 += w * e[sl];
        }
        ssim_px(mu1, mu2, e11, e22, e12, sacc, cacc);
    }

    // ---- reduction ----
    #pragma unroll
    for (int off = 16; off; off >>= 1) {
        sacc += __shfl_down_sync(0xffffffffu, sacc, off);
        cacc += __shfl_down_sync(0xffffffffu, cacc, off);
    }
    if (tx == 0) { red[0][ty] = sacc; red[1][ty] = cacc; }
    __syncthreads();
    if (tid == 0) {
        float ss = 0.f, cc = 0.f;
        #pragma unroll
        for (int i = 0; i < 8; i++) { ss += red[0][i]; cc += red[1][i]; }
        atomicAdd(&g_acc_ssim[level], (double)ss);
        atomicAdd(&g_acc_cs[level], (double)cc);
    }
}

// ---------------------------------------------------------------------------
// Fused small-level kernel: levels 2,3,4 — one block per plane.
// Dynamic SMEM float2 buffers:
//   A: 132x132 (padded 128) @ 0       (17424 float2)
//   B:  68x68  (padded  64) @ 17424   ( 4624 float2)
//   C:  36x36  (padded  32) @ 22048   ( 1296 float2)
// ---------------------------------------------------------------------------
#define SM_FLOAT2 (17424 + 4624 + 1296)
#define SM_BYTES (SM_FLOAT2 * 8)

template<int S>
__device__ __forceinline__ void ssim_plane(const float2* __restrict__ P, int stride,
                                           int tx, int ty, float& sa, float& ca)
{
    constexpr int RPT = S / 8;
    const float gw[5] = {GW0, GW1, GW2, GW1, GW0};

    for (int ct = 0; ct < S / 32; ct++) {
        int c = tx + 32 * ct;
        int r0 = ty * RPT;
        float m[5][5];

        #pragma unroll
        for (int j = 0; j < 5; j++) {
            const float2* p = P + (r0 + j) * stride + c;   // row r0-2+j (padded +2)
            float a0 = 0.f, a1 = 0.f, a2 = 0.f, a3 = 0.f, a4 = 0.f;
            #pragma unroll
            for (int k = 0; k < 5; k++) {
                float2 v = p[k]; float w = gw[k];
                a0 += w * v.x; a1 += w * v.y;
                a2 += w * (v.x * v.x); a3 += w * (v.y * v.y); a4 += w * (v.x * v.y);
            }
            m[0][j] = a0; m[1][j] = a1; m[2][j] = a2; m[3][j] = a3; m[4][j] = a4;
        }

        #pragma unroll
        for (int i = 0; i < RPT; i++) {
            if (i > 0) {
                int sl = (i + 4) % 5;
                const float2* p = P + (r0 + i + 4) * stride + c;  // row r0+i+2
                float a0 = 0.f, a1 = 0.f, a2 = 0.f, a3 = 0.f, a4 = 0.f;
                #pragma unroll
                for (int k = 0; k < 5; k++) {
                    float2 v = p[k]; float w = gw[k];
                    a0 += w * v.x; a1 += w * v.y;
                    a2 += w * (v.x * v.x); a3 += w * (v.y * v.y); a4 += w * (v.x * v.y);
                }
                m[0][sl] = a0; m[1][sl] = a1; m[2][sl] = a2; m[3][sl] = a3; m[4][sl] = a4;
            }
            float mu1 = 0.f, mu2 = 0.f, e11 = 0.f, e22 = 0.f, e12 = 0.f;
            #pragma unroll
            for (int k = 0; k < 5; k++) {
                int sl = (i + k) % 5;
                float w = gw[k];
                mu1 += w * m[0][sl]; mu2 += w * m[1][sl];
                e11 += w * m[2][sl]; e22 += w * m[3][sl]; e12 += w * m[4][sl];
            }
            ssim_px(mu1, mu2, e11, e22, e12, sa, ca);
        }
    }
}

__global__ void __launch_bounds__(256)
ssim_small()
{
    extern __shared__ float2 sm[];
    float2* A = sm;
    float2* B = sm + 17424;
    float2* C = sm + 17424 + 4624;
    __shared__ float red[6][8];

    const int tx = threadIdx.x, ty = threadIdx.y;
    const int tid = ty * 32 + tx;
    const int plane = blockIdx.x;

    const float* p1 = g_b1 + OFF_L2 + (size_t)plane * L2_PER;
    const float* p2 = g_b2 + OFF_L2 + (size_t)plane * L2_PER;

    // zero B and C (their 2-wide borders must be 0; zero everything, cheap)
    for (int idx = tid; idx < 4624 + 1296; idx += 256) {
        if (idx < 4624) B[idx] = make_float2(0.f, 0.f);
        else            C[idx - 4624] = make_float2(0.f, 0.f);
    }
    // load A (132x132 padded): border zeros
    for (int idx = tid; idx < 17424; idx += 256) {
        int r = idx / 132, c = idx - 132 * r;
        int gr = r - 2, gc = c - 2;
        float2 v = make_float2(0.f, 0.f);
        if ((gr >= 0) & (gr < 128) & (gc >= 0) & (gc < 128)) {
            int g = gr * 128 + gc;
            v = make_float2(p1[g], p2[g]);
        }
        A[idx] = v;
    }
    __syncthreads();

    float s2 = 0.f, c2 = 0.f, s3 = 0.f, c3 = 0.f, s4 = 0.f, c4 = 0.f;

    // level 2 SSIM on A
    ssim_plane<128>(A, 132, tx, ty, s2, c2);
    // pool A -> B (reads A, writes interior of B; no conflict with ssim reads)
    for (int idx = tid; idx < 4096; idx += 256) {
        int i = idx >> 6, j = idx & 63;
        int base = (2 * i + 2) * 132 + (2 * j + 2);
        float2 a = A[base], b = A[base + 1], c = A[base + 132], d = A[base + 133];
        B[(i + 2) * 68 + j + 2] =
            make_float2(0.25f * (a.x + b.x + c.x + d.x),
                        0.25f * (a.y + b.y + c.y + d.y));
    }
    __syncthreads();

    // level 3 SSIM on B
    ssim_plane<64>(B, 68, tx, ty, s3, c3);
    // pool B -> C
    for (int idx = tid; idx < 1024; idx += 256) {
        int i = idx >> 5, j = idx & 31;
        int base = (2 * i + 2) * 68 + (2 * j + 2);
        float2 a = B[base], b = B[base + 1], c = B[base + 68], d = B[base + 69];
        C[(i + 2) * 36 + j + 2] =
            make_float2(0.25f * (a.x + b.x + c.x + d.x),
                        0.25f * (a.y + b.y + c.y + d.y));
    }
    __syncthreads();

    // level 4 SSIM on C
    ssim_plane<32>(C, 36, tx, ty, s4, c4);

    // reduction of 6 partials
    float vals[6] = {s2, c2, s3, c3, s4, c4};
    #pragma unroll
    for (int v = 0; v < 6; v++) {
        float x = vals[v];
        #pragma unroll
        for (int off = 16; off; off >>= 1)
            x += __shfl_down_sync(0xffffffffu, x, off);
        if (tx == 0) red[v][ty] = x;
        vals[v] = x;
    }
    __syncthreads();
    if (tid == 0) {
        float t[6] = {0.f, 0.f, 0.f, 0.f, 0.f, 0.f};
        #pragma unroll
        for (int i = 0; i < 8; i++)
            #pragma unroll
            for (int v = 0; v < 6; v++) t[v] += red[v][i];
        atomicAdd(&g_acc_ssim[2], (double)t[0]);
        atomicAdd(&g_acc_cs[2],   (double)t[1]);
        atomicAdd(&g_acc_ssim[3], (double)t[2]);
        atomicAdd(&g_acc_cs[3],   (double)t[3]);
        atomicAdd(&g_acc_ssim[4], (double)t[4]);
        atomicAdd(&g_acc_cs[4],   (double)t[5]);
    }
}

__global__ void finalize_kernel(float* __restrict__ out)
{
    const double w[5] = {(double)0.0448f, (double)0.2856f, (double)0.3001f,
                         (double)0.2363f, (double)0.1333f};
    double cnt4 = (double)NC * 32.0 * 32.0;
    double s4 = g_acc_ssim[4] / cnt4;
    double ss4 = (s4 + 1.0) * 0.5;
    double p2 = pow(ss4, w[4]);

    double res = 1.0;
    #pragma unroll
    for (int i = 0; i < 4; i++) {
        int dim = 512 >> i;
        double cnt = (double)NC * (double)dim * (double)dim;
        double cs = g_acc_cs[i] / cnt;
        double m = (cs + 1.0) * 0.5;
        res *= pow(m, w[i]) * p2;
    }
    out[0] = (float)res;
}

extern "C" void kernel_launch(void* const* d_in, const int* in_sizes, int n_in,
                              void* d_out, int out_size)
{
    const float* img1 = (const float*)d_in[0];
    const float* img2 = (const float*)d_in[1];
    float* out = (float*)d_out;

    cudaFuncSetAttribute(ssim_small,
                         cudaFuncAttributeMaxDynamicSharedMemorySize, SM_BYTES);

    zero_acc_kernel<<<1, 32>>>();

    dim3 blk(32, 8);
    ssim_big<<<dim3(16, 16, NC), blk>>>(img1, img2, 0, OFF_L1, 512, 512, 0);
    ssim_big<<<dim3(8, 8, NC), blk>>>(nullptr, nullptr, OFF_L1, OFF_L2, 256, 256, 1);
    ssim_small<<<NC, blk, SM_BYTES>>>();
    finalize_kernel<<<1, 1>>>(out);
}

// round 3
// speedup vs baseline: 1.3153x; 1.1798x over previous
#include <cuda_runtime.h>
#include <math.h>

// ---------------------------------------------------------------------------
// MS-SSIM on (32,3,512,512) fp32, 5 levels. Packed f32x2 (FFMA2) math:
// both images ride in one 64-bit register lane-pair everywhere.
// L0, L1: tiled kernel (32x32 tile, fused 2x2 pool).
// L2+L3+L4: single fused kernel, whole plane pyramid in SMEM, 512 threads.
// ---------------------------------------------------------------------------

#define NC 96
#define L1_PER 65536            // 256*256
#define L2_PER 16384            // 128*128
#define OFF_L1 0
#define OFF_L2 (NC * L1_PER)
#define BUF_TOT (OFF_L2 + NC * L2_PER)

__device__ float g_b1[BUF_TOT];
__device__ float g_b2[BUF_TOT];
__device__ double g_acc_ssim[5];
__device__ double g_acc_cs[5];

// Gaussian(sigma=1.5) 5-tap normalized
#define GW0 0.12007838424321349f
#define GW1 0.23388075658535032f
#define GW2 0.29208171834287243f
#define C1V (0.01f * 0.01f)
#define C2V (0.03f * 0.03f)

typedef unsigned long long u64;

__device__ __forceinline__ u64 pk2(float lo, float hi) {
    u64 r; asm("mov.b64 %0, {%1, %2};" : "=l"(r) : "f"(lo), "f"(hi)); return r;
}
__device__ __forceinline__ void upk2(u64 v, float& lo, float& hi) {
    asm("mov.b64 {%0, %1}, %2;" : "=f"(lo), "=f"(hi) : "l"(v));
}
__device__ __forceinline__ u64 fma2_(u64 a, u64 b, u64 c) {
    u64 d; asm("fma.rn.f32x2 %0, %1, %2, %3;" : "=l"(d) : "l"(a), "l"(b), "l"(c)); return d;
}
__device__ __forceinline__ u64 mul2_(u64 a, u64 b) {
    u64 d; asm("mul.rn.f32x2 %0, %1, %2;" : "=l"(d) : "l"(a), "l"(b)); return d;
}
__device__ __forceinline__ u64 add2_(u64 a, u64 b) {
    u64 d; asm("add.rn.f32x2 %0, %1, %2;" : "=l"(d) : "l"(a), "l"(b)); return d;
}

__global__ void zero_acc_kernel() {
    int i = threadIdx.x;
    if (i < 5) { g_acc_ssim[i] = 0.0; g_acc_cs[i] = 0.0; }
}

// horizontal 5-tap Gaussian moments from packed (x,y) pixels
__device__ __forceinline__ void hmoments(const float2* __restrict__ p,
                                         u64 w0p, u64 w1p, u64 w2p,
                                         u64& a01, u64& a23, float& a4)
{
    a01 = 0ull; a23 = 0ull; a4 = 0.f;
    #pragma unroll
    for (int k = 0; k < 5; k++) {
        u64 v = *reinterpret_cast<const u64*>(p + k);
        u64 wp = (k == 0 || k == 4) ? w0p : ((k == 1 || k == 3) ? w1p : w2p);
        float w = (k == 0 || k == 4) ? GW0 : ((k == 1 || k == 3) ? GW1 : GW2);
        u64 xxyy = mul2_(v, v);
        a01 = fma2_(wp, v, a01);
        a23 = fma2_(wp, xxyy, a23);
        float x, y; upk2(v, x, y);
        a4 = fmaf(w, x * y, a4);
    }
}

__device__ __forceinline__ void ssim_px(u64 mu, u64 ee, float e12,
                                        float& sacc, float& cacc)
{
    float mu1, mu2; upk2(mu, mu1, mu2);
    u64 musq = mul2_(mu, mu);
    float mu1sq, mu2sq; upk2(musq, mu1sq, mu2sq);
    float e11, e22; upk2(ee, e11, e22);
    float mu12 = mu1 * mu2;
    float sg12 = e12 - mu12;
    float csn = fmaf(2.f, sg12, C2V);
    float csd = (e11 - mu1sq) + (e22 - mu2sq) + C2V;
    float lnum = fmaf(2.f, mu12, C1V);
    float lden = mu1sq + mu2sq + C1V;
    float cs = __fdividef(csn, csd);
    sacc = fmaf(__fdividef(lnum, lden), cs, sacc);
    cacc += cs;
}

// ---------------------------------------------------------------------------
// Big-level kernel (levels 0 and 1): 32x32 tile, 256 threads
// ---------------------------------------------------------------------------
__global__ void __launch_bounds__(256)
ssim_big(const float* __restrict__ ext1, const float* __restrict__ ext2,
         int inOff, int outOff, int W, int H, int level)
{
    __shared__ float2 s[36][36];     // packed (img1, img2) halo tile
    __shared__ float2 hA[36][32];    // (mu1h, mu2h)
    __shared__ float2 hB[36][32];    // (e11h, e22h)
    __shared__ float  hC[36][32];    // e12h
    __shared__ float  red[2][8];

    const int tx = threadIdx.x, ty = threadIdx.y;
    const int tid = ty * 32 + tx;
    const int ox = blockIdx.x * 32, oy = blockIdx.y * 32;
    const int plane = blockIdx.z;

    const size_t planeOff = (size_t)plane * W * H;
    const float* p1 = ext1 ? (ext1 + planeOff) : (g_b1 + inOff + planeOff);
    const float* p2 = ext2 ? (ext2 + planeOff) : (g_b2 + inOff + planeOff);

    const u64 w0p = pk2(GW0, GW0), w1p = pk2(GW1, GW1), w2p = pk2(GW2, GW2);

    // ---- stage 1: load 36x36 halo ----
    bool interior = (ox >= 2) & (oy >= 2) & (ox + 34 <= W) & (oy + 34 <= H);
    if (interior) {
        // vectorized: 648 float2-pair loads, STS.128 stores
        #pragma unroll
        for (int it = 0; it < 3; it++) {
            int idx = tid + it * 256;
            if (idx < 648) {
                int r = idx / 18, pc = idx - 18 * r;
                size_t g = (size_t)(oy + r - 2) * W + (ox + 2 * pc - 2);
                float2 a = *reinterpret_cast<const float2*>(p1 + g);
                float2 b = *reinterpret_cast<const float2*>(p2 + g);
                *reinterpret_cast<float4*>(&s[r][2 * pc]) =
                    make_float4(a.x, b.x, a.y, b.y);
            }
        }
    } else {
        #pragma unroll
        for (int it = 0; it < 6; it++) {
            int idx = tid + it * 256;
            if (idx < 1296) {
                int r = idx / 36, c = idx - 36 * r;
                int gy = oy + r - 2, gx = ox + c - 2;
                float2 v = make_float2(0.f, 0.f);
                if ((gy >= 0) & (gy < H) & (gx >= 0) & (gx < W)) {
                    size_t g = (size_t)gy * W + gx;
                    v = make_float2(p1[g], p2[g]);
                }
                s[r][c] = v;
            }
        }
    }
    __syncthreads();

    // ---- stage 2: horizontal Gaussian moments (packed) ----
    for (int r = ty; r < 36; r += 8) {
        u64 a01, a23; float a4;
        hmoments(&s[r][tx], w0p, w1p, w2p, a01, a23, a4);
        *reinterpret_cast<u64*>(&hA[r][tx]) = a01;
        *reinterpret_cast<u64*>(&hB[r][tx]) = a23;
        hC[r][tx] = a4;
    }
    __syncthreads();

    // ---- fused 2x2 avg-pool -> next level ----
    {
        int pr = tid >> 4, pc = tid & 15;
        int r0 = 2 + 2 * pr, c0 = 2 + 2 * pc;
        u64 a = *reinterpret_cast<const u64*>(&s[r0][c0]);
        u64 b = *reinterpret_cast<const u64*>(&s[r0][c0 + 1]);
        u64 c = *reinterpret_cast<const u64*>(&s[r0 + 1][c0]);
        u64 d = *reinterpret_cast<const u64*>(&s[r0 + 1][c0 + 1]);
        u64 sum = add2_(add2_(a, b), add2_(c, d));
        u64 q = mul2_(pk2(0.25f, 0.25f), sum);
        float v1, v2; upk2(q, v1, v2);
        int Wh = W >> 1, Hh = H >> 1;
        size_t o = (size_t)outOff + (size_t)plane * Wh * Hh
                 + (size_t)(oy / 2 + pr) * Wh + (ox / 2 + pc);
        g_b1[o] = v1;
        g_b2[o] = v2;
    }

    // ---- stage 3: vertical pass, register ring, 4 consecutive rows/thread ----
    const int b = ty * 4;
    u64 q01[5], q23[5]; float e[5];
    #pragma unroll
    for (int j = 0; j < 5; j++) {
        q01[j] = *reinterpret_cast<const u64*>(&hA[b + j][tx]);
        q23[j] = *reinterpret_cast<const u64*>(&hB[b + j][tx]);
        e[j] = hC[b + j][tx];
    }

    float sacc = 0.f, cacc = 0.f;
    #pragma unroll
    for (int i = 0; i < 4; i++) {
        if (i > 0) {
            int sl = (i + 4) % 5;
            q01[sl] = *reinterpret_cast<const u64*>(&hA[b + i + 4][tx]);
            q23[sl] = *reinterpret_cast<const u64*>(&hB[b + i + 4][tx]);
            e[sl] = hC[b + i + 4][tx];
        }
        u64 mu = 0ull, ee = 0ull; float e12 = 0.f;
        #pragma unroll
        for (int k = 0; k < 5; k++) {
            int sl = (i + k) % 5;
            u64 wp = (k == 0 || k == 4) ? w0p : ((k == 1 || k == 3) ? w1p : w2p);
            float w = (k == 0 || k == 4) ? GW0 : ((k == 1 || k == 3) ? GW1 : GW2);
            mu = fma2_(wp, q01[sl], mu);
            ee = fma2_(wp, q23[sl], ee);
            e12 = fmaf(w, e[sl], e12);
        }
        ssim_px(mu, ee, e12, sacc, cacc);
    }

    // ---- reduction ----
    #pragma unroll
    for (int off = 16; off; off >>= 1) {
        sacc += __shfl_down_sync(0xffffffffu, sacc, off);
        cacc += __shfl_down_sync(0xffffffffu, cacc, off);
    }
    if (tx == 0) { red[0][ty] = sacc; red[1][ty] = cacc; }
    __syncthreads();
    if (tid == 0) {
        float ss = 0.f, cc = 0.f;
        #pragma unroll
        for (int i = 0; i < 8; i++) { ss += red[0][i]; cc += red[1][i]; }
        atomicAdd(&g_acc_ssim[level], (double)ss);
        atomicAdd(&g_acc_cs[level], (double)cc);
    }
}

// ---------------------------------------------------------------------------
// Fused small-level kernel: levels 2,3,4 — one block per plane, 512 threads.
//   A: 132x132 (padded 128) @ 0       (17424 float2)
//   B:  68x68  (padded  64) @ 17424   ( 4624 float2)
//   C:  36x36  (padded  32) @ 22048   ( 1296 float2)
// ---------------------------------------------------------------------------
#define SM_FLOAT2 (17424 + 4624 + 1296)
#define SM_BYTES (SM_FLOAT2 * 8)
#define SMALL_T 512

template<int S, int NW>
__device__ __forceinline__ void ssim_plane(const float2* __restrict__ P, int stride,
                                           int tx, int ty, float& sa, float& ca)
{
    constexpr int RPT = S / NW;
    const u64 w0p = pk2(GW0, GW0), w1p = pk2(GW1, GW1), w2p = pk2(GW2, GW2);

    #pragma unroll
    for (int ct = 0; ct < S / 32; ct++) {
        int c = tx + 32 * ct;
        int r0 = ty * RPT;
        u64 m01[5], m23[5]; float m4[5];

        #pragma unroll
        for (int j = 0; j < 5; j++)
            hmoments(P + (r0 + j) * stride + c, w0p, w1p, w2p, m01[j], m23[j], m4[j]);

        #pragma unroll
        for (int i = 0; i < RPT; i++) {
            if (i > 0) {
                int sl = (i + 4) % 5;
                hmoments(P + (r0 + i + 4) * stride + c, w0p, w1p, w2p,
                         m01[sl], m23[sl], m4[sl]);
            }
            u64 mu = 0ull, ee = 0ull; float e12 = 0.f;
            #pragma unroll
            for (int k = 0; k < 5; k++) {
                int sl = (i + k) % 5;
                u64 wp = (k == 0 || k == 4) ? w0p : ((k == 1 || k == 3) ? w1p : w2p);
                float w = (k == 0 || k == 4) ? GW0 : ((k == 1 || k == 3) ? GW1 : GW2);
                mu = fma2_(wp, m01[sl], mu);
                ee = fma2_(wp, m23[sl], ee);
                e12 = fmaf(w, m4[sl], e12);
            }
            ssim_px(mu, ee, e12, sa, ca);
        }
    }
}

__global__ void __launch_bounds__(SMALL_T)
ssim_small()
{
    extern __shared__ float2 sm[];
    float2* A = sm;
    float2* B = sm + 17424;
    float2* C = sm + 17424 + 4624;
    __shared__ float red[6][16];

    const int tx = threadIdx.x, ty = threadIdx.y;
    const int tid = ty * 32 + tx;
    const int plane = blockIdx.x;

    const float* p1 = g_b1 + OFF_L2 + (size_t)plane * L2_PER;
    const float* p2 = g_b2 + OFF_L2 + (size_t)plane * L2_PER;

    // zero B and C (borders must be 0)
    for (int idx = tid; idx < 4624 + 1296; idx += SMALL_T) {
        if (idx < 4624) B[idx] = make_float2(0.f, 0.f);
        else            C[idx - 4624] = make_float2(0.f, 0.f);
    }
    // load A (132x132 padded)
    for (int idx = tid; idx < 17424; idx += SMALL_T) {
        int r = idx / 132, c = idx - 132 * r;
        int gr = r - 2, gc = c - 2;
        float2 v = make_float2(0.f, 0.f);
        if ((gr >= 0) & (gr < 128) & (gc >= 0) & (gc < 128)) {
            int g = gr * 128 + gc;
            v = make_float2(p1[g], p2[g]);
        }
        A[idx] = v;
    }
    __syncthreads();

    float s2 = 0.f, c2 = 0.f, s3 = 0.f, c3 = 0.f, s4 = 0.f, c4 = 0.f;

    ssim_plane<128, 16>(A, 132, tx, ty, s2, c2);
    // pool A -> B interior
    for (int idx = tid; idx < 4096; idx += SMALL_T) {
        int i = idx >> 6, j = idx & 63;
        int base = (2 * i + 2) * 132 + (2 * j + 2);
        u64 a = *reinterpret_cast<const u64*>(&A[base]);
        u64 b = *reinterpret_cast<const u64*>(&A[base + 1]);
        u64 c = *reinterpret_cast<const u64*>(&A[base + 132]);
        u64 d = *reinterpret_cast<const u64*>(&A[base + 133]);
        u64 q = mul2_(pk2(0.25f, 0.25f), add2_(add2_(a, b), add2_(c, d)));
        *reinterpret_cast<u64*>(&B[(i + 2) * 68 + j + 2]) = q;
    }
    __syncthreads();

    ssim_plane<64, 16>(B, 68, tx, ty, s3, c3);
    // pool B -> C interior
    for (int idx = tid; idx < 1024; idx += SMALL_T) {
        int i = idx >> 5, j = idx & 31;
        int base = (2 * i + 2) * 68 + (2 * j + 2);
        u64 a = *reinterpret_cast<const u64*>(&B[base]);
        u64 b = *reinterpret_cast<const u64*>(&B[base + 1]);
        u64 c = *reinterpret_cast<const u64*>(&B[base + 68]);
        u64 d = *reinterpret_cast<const u64*>(&B[base + 69]);
        u64 q = mul2_(pk2(0.25f, 0.25f), add2_(add2_(a, b), add2_(c, d)));
        *reinterpret_cast<u64*>(&C[(i + 2) * 36 + j + 2]) = q;
    }
    __syncthreads();

    ssim_plane<32, 16>(C, 36, tx, ty, s4, c4);

    // reduction of 6 partials
    float vals[6] = {s2, c2, s3, c3, s4, c4};
    #pragma unroll
    for (int v = 0; v < 6; v++) {
        float x = vals[v];
        #pragma unroll
        for (int off = 16; off; off >>= 1)
            x += __shfl_down_sync(0xffffffffu, x, off);
        if (tx == 0) red[v][ty] = x;
    }
    __syncthreads();
    if (tid == 0) {
        float t[6] = {0.f, 0.f, 0.f, 0.f, 0.f, 0.f};
        #pragma unroll
        for (int i = 0; i < 16; i++)
            #pragma unroll
            for (int v = 0; v < 6; v++) t[v] += red[v][i];
        atomicAdd(&g_acc_ssim[2], (double)t[0]);
        atomicAdd(&g_acc_cs[2],   (double)t[1]);
        atomicAdd(&g_acc_ssim[3], (double)t[2]);
        atomicAdd(&g_acc_cs[3],   (double)t[3]);
        atomicAdd(&g_acc_ssim[4], (double)t[4]);
        atomicAdd(&g_acc_cs[4],   (double)t[5]);
    }
}

__global__ void finalize_kernel(float* __restrict__ out)
{
    const double w[5] = {(double)0.0448f, (double)0.2856f, (double)0.3001f,
                         (double)0.2363f, (double)0.1333f};
    double cnt4 = (double)NC * 32.0 * 32.0;
    double s4 = g_acc_ssim[4] / cnt4;
    double ss4 = (s4 + 1.0) * 0.5;
    double p2 = pow(ss4, w[4]);

    double res = 1.0;
    #pragma unroll
    for (int i = 0; i < 4; i++) {
        int dim = 512 >> i;
        double cnt = (double)NC * (double)dim * (double)dim;
        double cs = g_acc_cs[i] / cnt;
        double m = (cs + 1.0) * 0.5;
        res *= pow(m, w[i]) * p2;
    }
    out[0] = (float)res;
}

extern "C" void kernel_launch(void* const* d_in, const int* in_sizes, int n_in,
                              void* d_out, int out_size)
{
    const float* img1 = (const float*)d_in[0];
    const float* img2 = (const float*)d_in[1];
    float* out = (float*)d_out;

    cudaFuncSetAttribute(ssim_small,
                         cudaFuncAttributeMaxDynamicSharedMemorySize, SM_BYTES);

    zero_acc_kernel<<<1, 32>>>();

    dim3 blk(32, 8);
    ssim_big<<<dim3(16, 16, NC), blk>>>(img1, img2, 0, OFF_L1, 512, 512, 0);
    ssim_big<<<dim3(8, 8, NC), blk>>>(nullptr, nullptr, OFF_L1, OFF_L2, 256, 256, 1);
    ssim_small<<<NC, dim3(32, 16), SM_BYTES>>>();
    finalize_kernel<<<1, 1>>>(out);
}